// round 7
// baseline (speedup 1.0000x reference)
#include <cuda_runtime.h>
#include <math.h>

#define BNH 32
#define LL  1024
#define DD  64
#define RR  129
#define TI  16
#define NT  512

#define PSTR 1028
#define KSTR 68
#define VSTR 72
#define GBUF 9216

// shared layout (float units):
//   q_s   [16][68]      @ 0       (1088)
//   av_s  [16][132]     @ 1088    (2112)   qe in phases A/B, av afterwards
//   posi  [16] int      @ 3200
//   posa  [1024] int    @ 3216
//   p_s   [16][1028]    @ 4240    (16448)  scores -> p(exact->tf32) -> flat partials [2][1024]
//   G     2 x 9216      @ 20688   (18432)  k-tiles[128][68] / a64[16][528] u64 / v-tiles[128][72]
//   emb_s [129][68]     @ 39120   (8772)   emb_k in phase A, emb_v afterwards
#define SMEM_FLOATS 47892
#define SMEM_BYTES  (SMEM_FLOATS * 4)

#define FIX_SCALE 4503599627370496.0f   /* 2^52 */
#define FIX_INV   (1.0f / 4503599627370496.0f)

__device__ __forceinline__ unsigned tf32b(float x) {
    unsigned u;
    asm("cvt.rna.tf32.f32 %0, %1;" : "=r"(u) : "f"(x));
    return u;
}
__device__ __forceinline__ float tf32r(float x) { return __uint_as_float(tf32b(x)); }
__device__ __forceinline__ float4 tf32r4(float4 a) {
    a.x = tf32r(a.x); a.y = tf32r(a.y); a.z = tf32r(a.z); a.w = tf32r(a.w);
    return a;
}

#define MMA_TF32(c0,c1,c2,c3,a0,a1,a2,a3,b0,b1)                               \
    asm volatile("mma.sync.aligned.m16n8k8.row.col.f32.tf32.tf32.f32 "        \
                 "{%0,%1,%2,%3}, {%4,%5,%6,%7}, {%8,%9}, {%0,%1,%2,%3};"      \
                 : "+f"(c0), "+f"(c1), "+f"(c2), "+f"(c3)                      \
                 : "r"(a0), "r"(a1), "r"(a2), "r"(a3), "r"(b0), "r"(b1))

extern "C" __global__ void __launch_bounds__(NT, 1)
attn_rel_kernel(const float* __restrict__ gq, const float* __restrict__ gk,
                const float* __restrict__ gv, const float* __restrict__ gw,
                const float* __restrict__ gek, const float* __restrict__ gev,
                const int* __restrict__ gpos, const unsigned char* __restrict__ gmask,
                float* __restrict__ gout, float* __restrict__ gp)
{
    extern __shared__ float sm[];
    float* q_s   = sm;
    float* av_s  = sm + 1088;
    int*   posi  = (int*)(sm + 3200);
    int*   posa  = (int*)(sm + 3216);
    float* p_s   = sm + 4240;
    float* G     = sm + 20688;
    float* emb_s = sm + 39120;

    const int b    = blockIdx.y;
    const int i0   = blockIdx.x * TI;
    const int tid  = threadIdx.x;
    const int lane = tid & 31;
    const int warp = tid >> 5;
    const unsigned FULL = 0xffffffffu;

    const int gid  = lane >> 2;     // fragment "groupID" 0..7
    const int tid4 = lane & 3;      // fragment thread-in-group 0..3

    // ---------------- loads: q tile (exact, stride 68), pos, emb_k ----------------
    {
        if (tid < 256) {
            const float4* q4 = (const float4*)(gq + ((size_t)b * LL + i0) * DD);
            int row = tid >> 4, c4 = tid & 15;
            *(float4*)(q_s + row * 68 + c4 * 4) = q4[tid];
        }
        if (tid < TI) posi[tid] = gpos[b * LL + i0 + tid];
        #pragma unroll
        for (int t = tid; t < LL; t += NT) posa[t] = gpos[b * LL + t];
        for (int e = tid; e < RR * DD; e += NT) {
            int r = e >> 6, d = e & 63;
            emb_s[r * 68 + d] = gek[e];
        }
    }
    __syncthreads();

    // ---------------- phase A: qe[i][r] = q[i] . emb_k[r]  (exact fp32) ----------------
    for (int e = tid; e < TI * RR; e += NT) {
        int i = e / RR, r = e - i * RR;
        const float4* qa = (const float4*)(q_s + i * 68);
        const float4* ea = (const float4*)(emb_s + r * 68);
        float acc = 0.f;
        #pragma unroll
        for (int c = 0; c < 16; c++) {
            float4 a = qa[c], e2 = ea[c];
            acc += a.x*e2.x + a.y*e2.y + a.z*e2.z + a.w*e2.w;
        }
        av_s[i * 132 + r] = acc;
    }

    // persistent tf32 A-fragments of q
    unsigned af[8][4];
    #pragma unroll
    for (int ks = 0; ks < 8; ks++) {
        af[ks][0] = tf32b(q_s[ gid      * 68 + ks * 8 + tid4    ]);
        af[ks][1] = tf32b(q_s[(gid + 8) * 68 + ks * 8 + tid4    ]);
        af[ks][2] = tf32b(q_s[ gid      * 68 + ks * 8 + tid4 + 4]);
        af[ks][3] = tf32b(q_s[(gid + 8) * 68 + ks * 8 + tid4 + 4]);
    }

    // prologue: k tile 0 -> G0 (tf32)
    {
        const float4* k4 = (const float4*)(gk + ((size_t)b * LL) * DD);
        #pragma unroll
        for (int s = 0; s < 4; s++) {
            int f = tid + s * NT;
            int row = f >> 4, d4 = f & 15;
            *(float4*)(G + row * KSTR + d4 * 4) = tf32r4(k4[f]);
        }
    }
    __syncthreads();

    // ---------------- phase B: scores = (QK^T + qe[table] + attn_w)/8, mask ----------------
    const int jbase = warp * 8;                 // 8 j columns per warp per 128-tile
    const int i_lo = gid, i_hi = gid + 8;
    const int pi_lo = posi[i_lo], pi_hi = posi[i_hi];
    const size_t row_lo = ((size_t)b * LL + (i0 + i_lo)) * LL;
    const size_t row_hi = ((size_t)b * LL + (i0 + i_hi)) * LL;

    for (int jt = 0; jt < 8; jt++) {
        const float* Gc = G + (jt & 1) * GBUF;

        // prefetch next k tile into registers (latency hidden behind mma+epilogue)
        float4 rn[4];
        if (jt < 7) {
            const float4* k4 = (const float4*)(gk + ((size_t)b * LL + (jt + 1) * 128) * DD);
            #pragma unroll
            for (int s = 0; s < 4; s++) rn[s] = k4[tid + s * NT];
        }

        // prefetch attn_w / mask for this tile's epilogue
        const int jg0 = jt * 128 + jbase + tid4 * 2;
        float2 w_lo = *(const float2*)(gw + row_lo + jg0);
        float2 w_hi = *(const float2*)(gw + row_hi + jg0);
        uchar2 m_lo = *(const uchar2*)(gmask + row_lo + jg0);
        uchar2 m_hi = *(const uchar2*)(gmask + row_hi + jg0);

        float c0 = 0.f, c1 = 0.f, c2 = 0.f, c3 = 0.f;
        #pragma unroll
        for (int ks = 0; ks < 8; ks++) {
            const float* kb = Gc + (jbase + gid) * KSTR + ks * 8 + tid4;
            unsigned b0 = __float_as_uint(kb[0]);
            unsigned b1 = __float_as_uint(kb[4]);
            MMA_TF32(c0, c1, c2, c3,
                     af[ks][0], af[ks][1], af[ks][2], af[ks][3], b0, b1);
        }

        // epilogue: rel-pos gather + attn_w, scale, mask, store to p_s
        {
            int pj0 = posa[jg0], pj1 = posa[jg0 + 1];
            int d00 = max(-64, min(64, pj0 - pi_lo)) + 64;
            int d01 = max(-64, min(64, pj1 - pi_lo)) + 64;
            int d10 = max(-64, min(64, pj0 - pi_hi)) + 64;
            int d11 = max(-64, min(64, pj1 - pi_hi)) + 64;
            float s00 = (c0 + av_s[i_lo * 132 + d00] + w_lo.x) * 0.125f;
            float s01 = (c1 + av_s[i_lo * 132 + d01] + w_lo.y) * 0.125f;
            float s10 = (c2 + av_s[i_hi * 132 + d10] + w_hi.x) * 0.125f;
            float s11 = (c3 + av_s[i_hi * 132 + d11] + w_hi.y) * 0.125f;
            if (m_lo.x) s00 = -INFINITY;
            if (m_lo.y) s01 = -INFINITY;
            if (m_hi.x) s10 = -INFINITY;
            if (m_hi.y) s11 = -INFINITY;
            *(float2*)(p_s + i_lo * PSTR + jg0) = make_float2(s00, s01);
            *(float2*)(p_s + i_hi * PSTR + jg0) = make_float2(s10, s11);
        }
        __syncthreads();
        if (jt < 7) {
            float* Gn = G + ((jt + 1) & 1) * GBUF;
            #pragma unroll
            for (int s = 0; s < 4; s++) {
                int f = tid + s * NT;
                int row = f >> 4, d4 = f & 15;
                *(float4*)(Gn + row * KSTR + d4 * 4) = tf32r4(rn[s]);
            }
            __syncthreads();
        }
    }

    // swap emb_k -> emb_v (read only in the final out stage; syncs below cover it)
    for (int e = tid; e < RR * DD; e += NT) {
        int r = e >> 6, d = e & 63;
        emb_s[r * 68 + d] = gev[e];
    }

    // prefetch v tile 0 into registers; STS after phase C (hidden behind softmax)
    float4 v0[4];
    {
        const float4* v4 = (const float4*)(gv + ((size_t)b * LL) * DD);
        #pragma unroll
        for (int s = 0; s < 4; s++) v0[s] = v4[tid + s * NT];
    }

    // ---------------- phase C: softmax + p write + av scatter + tf32-round p ----------------
    {
        const int i = warp;                     // 16 warps, one row each
        float* row = p_s + i * PSTR;
        float m = -INFINITY;
        #pragma unroll
        for (int c = 0; c < 32; c++) m = fmaxf(m, row[lane + 32*c]);
        #pragma unroll
        for (int o = 16; o > 0; o >>= 1) m = fmaxf(m, __shfl_xor_sync(FULL, m, o));

        float sum = 0.f;
        #pragma unroll
        for (int c = 0; c < 32; c++) {
            float e = __expf(row[lane + 32*c] - m);
            row[lane + 32*c] = e;
            sum += e;
        }
        #pragma unroll
        for (int o = 16; o > 0; o >>= 1) sum += __shfl_xor_sync(FULL, sum, o);
        float inv = 1.0f / sum;

        size_t prow = ((size_t)b * LL + (i0 + i)) * LL;
        #pragma unroll
        for (int c = 0; c < 32; c++) {
            float pv = row[lane + 32*c] * inv;
            row[lane + 32*c] = pv;
            if (gp) gp[prow + lane + 32*c] = pv;
        }

        // fixed-point scatter into 129 buckets, 4 banks per bucket (exact -> deterministic)
        unsigned long long* a64 = (unsigned long long*)G + (size_t)i * 528;
        for (int idx = lane; idx < 528; idx += 32) a64[idx] = 0ull;
        __syncwarp();

        int pi = posi[i];
        const int bank = lane & 3;
        #pragma unroll
        for (int c = 0; c < 32; c++) {
            int j = lane + 32*c;
            int diff = posa[j] - pi;
            diff = max(-64, min(64, diff));
            unsigned long long qv = (unsigned long long)(row[j] * FIX_SCALE);
            atomicAdd(a64 + (diff + 64) * 4 + bank, qv);
        }
        __syncwarp();

        #pragma unroll
        for (int c = 0; c < 5; c++) {
            int idx = lane + 32*c;
            if (idx < RR) {
                unsigned long long t = a64[idx*4] + a64[idx*4+1]
                                     + a64[idx*4+2] + a64[idx*4+3];
                av_s[i * 132 + idx] = __ull2float_rn(t) * FIX_INV;
            }
        }
        __syncwarp();

        // round p row to tf32 in place for the P@V mma (gp holds exact p)
        #pragma unroll
        for (int c = 0; c < 32; c++)
            row[lane + 32*c] = tf32r(row[lane + 32*c]);
    }
    __syncthreads();

    // STS prefetched v tile 0 -> G0
    {
        #pragma unroll
        for (int s = 0; s < 4; s++) {
            int f = tid + s * NT;
            int row = f >> 4, d4 = f & 15;
            *(float4*)(G + row * VSTR + d4 * 4) = tf32r4(v0[s]);
        }
    }
    __syncthreads();

    // ---------------- phase D: out = P @ V  (tf32 mma, double-buffered v tiles) ----------------
    const int ntile = warp & 7;                 // d-block of 8
    const int kh    = warp >> 3;                // j-half within each 128-tile
    float cd0 = 0.f, cd1 = 0.f, cd2 = 0.f, cd3 = 0.f;

    for (int jt = 0; jt < 8; jt++) {
        const float* Gc = G + (jt & 1) * GBUF;

        float4 rn[4];
        if (jt < 7) {
            const float4* v4 = (const float4*)(gv + ((size_t)b * LL + (jt + 1) * 128) * DD);
            #pragma unroll
            for (int s = 0; s < 4; s++) rn[s] = v4[tid + s * NT];
        }

        #pragma unroll
        for (int ks = 0; ks < 8; ks++) {
            int jrow = kh * 64 + ks * 8;                // within tile
            int jcol = jt * 128 + jrow + tid4;          // global j
            unsigned a0 = __float_as_uint(p_s[ gid      * PSTR + jcol    ]);
            unsigned a1 = __float_as_uint(p_s[(gid + 8) * PSTR + jcol    ]);
            unsigned a2 = __float_as_uint(p_s[ gid      * PSTR + jcol + 4]);
            unsigned a3 = __float_as_uint(p_s[(gid + 8) * PSTR + jcol + 4]);
            const float* vb = Gc + (jrow + tid4) * VSTR + ntile * 8 + gid;
            unsigned b0 = __float_as_uint(vb[0]);
            unsigned b1 = __float_as_uint(vb[4 * VSTR]);
            MMA_TF32(cd0, cd1, cd2, cd3, a0, a1, a2, a3, b0, b1);
        }
        __syncthreads();
        if (jt < 7) {
            float* Gn = G + ((jt + 1) & 1) * GBUF;
            #pragma unroll
            for (int s = 0; s < 4; s++) {
                int f = tid + s * NT;
                int row = f >> 4, d4 = f & 15;
                *(float4*)(Gn + row * VSTR + d4 * 4) = tf32r4(rn[s]);
            }
            __syncthreads();
        }
    }

    // write the two kh partials into p_s (flat [2][16][64]; p_s is free now)
    {
        int d0 = ntile * 8 + tid4 * 2;
        float* P = p_s + kh * 1024;
        *(float2*)(P +  gid      * 64 + d0) = make_float2(cd0, cd1);
        *(float2*)(P + (gid + 8) * 64 + d0) = make_float2(cd2, cd3);
    }
    __syncthreads();

    if (gout) {
        #pragma unroll
        for (int c = 0; c < 2; c++) {
            int o = tid + 512 * c;            // 0..1023
            int i = o >> 6, d = o & 63;
            float s = p_s[o] + p_s[1024 + o];
            const float* avr = av_s + i * 132;
            const float* er  = emb_s + d;
            float s2 = 0.f;
            #pragma unroll 8
            for (int r = 0; r < RR; r++) s2 += avr[r] * er[r * 68];
            gout[((size_t)b * LL + i0 + i) * DD + d] = s + s2;
        }
    }
}

extern "C" void kernel_launch(void* const* d_in, const int* in_sizes, int n_in,
                              void* d_out, int out_size)
{
    const float* q   = (const float*)d_in[0];
    const float* k   = (const float*)d_in[1];
    const float* v   = (const float*)d_in[2];
    const float* w   = (const float*)d_in[3];
    const float* ek  = (const float*)d_in[4];
    const float* ev  = (const float*)d_in[5];
    const int*   pos = (const int*)d_in[6];
    const unsigned char* mask = (const unsigned char*)d_in[7];

    const long OUT_N = (long)BNH * LL * DD;   // 2,097,152
    const long P_N   = (long)BNH * LL * LL;   // 33,554,432

    float* outp = nullptr;
    float* pp   = nullptr;
    if ((long)out_size == OUT_N) {
        outp = (float*)d_out;
    } else if ((long)out_size == P_N) {
        pp = (float*)d_out;
    } else {
        outp = (float*)d_out;
        pp   = (float*)d_out + OUT_N;
    }

    cudaFuncSetAttribute(attn_rel_kernel,
                         cudaFuncAttributeMaxDynamicSharedMemorySize, SMEM_BYTES);
    dim3 grid(LL / TI, BNH);
    attn_rel_kernel<<<grid, NT, SMEM_BYTES>>>(q, k, v, w, ek, ev, pos, mask, outp, pp);
}